// round 1
// baseline (speedup 1.0000x reference)
#include <cuda_runtime.h>
#include <math.h>

// RoIPooling: feature_map [B,C,FH,FW] f32, rois [N,5] f32 (bidx,x1,y1,x2,y2),
// img_h/img_w scalars -> out [N,C,7,7] f32.
// Shapes from the bench: B=2, C=256, FH=FW=50, N=128, IMG=800.

#define C_DIM 256
#define FH 50
#define FW 50
#define OH 7
#define OW 7

__device__ __forceinline__ float decode_dim(const void* p) {
    // scalar may arrive as int32 or float32; sniff the bits.
    int v = *reinterpret_cast<const int*>(p);
    if (v > 0 && v < 1000000) return (float)v;     // plausible int (e.g. 800 = 0x320)
    return __int_as_float(v);                       // else it was a float (800.f = 0x44480000)
}

__global__ void roipool_kernel(const float* __restrict__ feat,
                               const float* __restrict__ rois,
                               const void* __restrict__ img_h_p,
                               const void* __restrict__ img_w_p,
                               float* __restrict__ out,
                               int total) {
    int idx = blockIdx.x * blockDim.x + threadIdx.x;
    if (idx >= total) return;

    int ow = idx % OW;
    int oh = (idx / OW) % OH;
    int c  = (idx / (OW * OH)) % C_DIM;
    int n  = idx / (OW * OH * C_DIM);

    float img_h = decode_dim(img_h_p);
    float img_w = decode_dim(img_w_p);
    float sh = __fdiv_rn((float)FH, img_h);   // 50/800 = 0.0625 exact
    float sw = __fdiv_rn((float)FW, img_w);

    const float* r = rois + n * 5;
    int bidx = (int)r[0];
    // exact replication of reference: floor(roi * s) with a single rn-multiply,
    // then the torch-style clamps.
    int x1 = max((int)floorf(__fmul_rn(r[1], sw)), 0);
    int y1 = max((int)floorf(__fmul_rn(r[2], sh)), 0);
    int x2 = min((int)floorf(__fmul_rn(r[3], sw)), FW);
    int y2 = min((int)floorf(__fmul_rn(r[4], sh)), FH);

    float roi_w = (float)max(x2 - x1, 1);
    float roi_h = (float)max(y2 - y1, 1);
    float bh = __fdiv_rn(roi_h, (float)OH);
    float bw = __fdiv_rn(roi_w, (float)OW);

    float y1f = (float)y1;
    float x1f = (float)x1;
    // no FMA contraction: mul then add, each correctly rounded, matching jnp.
    int ys = (int)floorf(__fadd_rn(y1f, __fmul_rn((float)oh,        bh)));
    int ye = (int)floorf(__fadd_rn(y1f, __fmul_rn((float)(oh + 1),  bh)));
    int xs = (int)floorf(__fadd_rn(x1f, __fmul_rn((float)ow,        bw)));
    int xe = (int)floorf(__fadd_rn(x1f, __fmul_rn((float)(ow + 1),  bw)));

    ys = min(max(ys, 0), FH - 1);
    ye = min(max(ye, 0), FH);
    xs = min(max(xs, 0), FW - 1);
    xe = min(max(xe, 0), FW);

    bool valid = (ye > ys) && (xe > xs);

    float m = -INFINITY;
    const float* plane = feat + ((size_t)bidx * C_DIM + c) * (FH * FW);
    for (int y = ys; y < ye; ++y) {
        const float* row = plane + y * FW;
        #pragma unroll 4
        for (int x = xs; x < xe; ++x) {
            m = fmaxf(m, __ldg(row + x));
        }
    }
    out[idx] = valid ? m : 0.0f;
}

extern "C" void kernel_launch(void* const* d_in, const int* in_sizes, int n_in,
                              void* d_out, int out_size) {
    const float* feat = (const float*)d_in[0];
    const float* rois = (const float*)d_in[1];
    const void*  imh  = d_in[2];
    const void*  imw  = d_in[3];
    float* out = (float*)d_out;

    int total = out_size;                 // N * C * OH * OW
    int threads = 256;
    int blocks = (total + threads - 1) / threads;
    roipool_kernel<<<blocks, threads>>>(feat, rois, imh, imw, out, total);
}